// round 16
// baseline (speedup 1.0000x reference)
#include <cuda_runtime.h>
#include <cuda_bf16.h>
#include <mma.h>
#include <cstdint>

using namespace nvcuda;

#define NN      131072
#define NG      256
#define HID     512
#define HID2    1024
#define NE      2097152
#define OFF_L   ((size_t)NN * 256)
#define OFF_E   (OFF_L + NN)

// -------- scratch (device globals: allocation-free per harness rules) ------
__device__ float          g_z[(size_t)NN * HID2];        // 512 MB
__device__ float          g_logits[NN];
__device__ unsigned char  g_keep[NN];
__device__ int            g_start[NG + 1];
__device__ __align__(16) __nv_bfloat16 g_A[(size_t)NN * 1024];    // 256 MB [Ah|Am]
__device__ __align__(16) __nv_bfloat16 g_B[(size_t)HID2 * 1024];  //   2 MB [Bh|Bm]

// ======================= PTX helpers ========================================
__device__ __forceinline__ uint32_t smem_u32(const void* p) {
    uint32_t a;
    asm("{ .reg .u64 t; cvta.to.shared.u64 t, %1; cvt.u32.u64 %0, t; }" : "=r"(a) : "l"(p));
    return a;
}
__device__ __forceinline__ void cp16(void* sdst, const void* gsrc) {
    asm volatile("cp.async.cg.shared.global [%0], [%1], 16;"
                 :: "r"(smem_u32(sdst)), "l"(gsrc) : "memory");
}
#define CP_COMMIT()  asm volatile("cp.async.commit_group;" ::: "memory")
#define CP_WAIT(n)   asm volatile("cp.async.wait_group %0;" :: "n"(n) : "memory")

// ============================================================================
// Pre-split: fp32 -> (hi, mid) bf16 residual pair
// ============================================================================
__device__ __forceinline__ void split8_hm(const float* a, uint4& H, uint4& M) {
    unsigned short hb[8], mb[8];
    #pragma unroll
    for (int i = 0; i < 8; i++) {
        float f = a[i];
        __nv_bfloat16 bh = __float2bfloat16_rn(f);
        float r1 = f - __bfloat162float(bh);
        __nv_bfloat16 bm = __float2bfloat16_rn(r1);
        hb[i] = __bfloat16_as_ushort(bh);
        mb[i] = __bfloat16_as_ushort(bm);
    }
    H = make_uint4(hb[0] | (uint32_t)hb[1] << 16, hb[2] | (uint32_t)hb[3] << 16,
                   hb[4] | (uint32_t)hb[5] << 16, hb[6] | (uint32_t)hb[7] << 16);
    M = make_uint4(mb[0] | (uint32_t)mb[1] << 16, mb[2] | (uint32_t)mb[3] << 16,
                   mb[4] | (uint32_t)mb[5] << 16, mb[6] | (uint32_t)mb[7] << 16);
}

__global__ __launch_bounds__(256) void presplitA_kernel(const float* __restrict__ h) {
    const size_t t = (size_t)blockIdx.x * 256 + threadIdx.x;
    const int row = (int)(t >> 6), kg = (int)(t & 63);
    float a[8];
    *(float4*)&a[0] = __ldcs((const float4*)(h + (size_t)row * HID + kg * 8));
    *(float4*)&a[4] = __ldcs((const float4*)(h + (size_t)row * HID + kg * 8 + 4));
    uint4 H, M;
    split8_hm(a, H, M);
    __nv_bfloat16* dst = g_A + (size_t)row * 1024 + kg * 8;
    *(uint4*)(dst)       = H;
    *(uint4*)(dst + 512) = M;
}

__global__ __launch_bounds__(256) void presplitB_kernel(const float* __restrict__ W1) {
    const int t = blockIdx.x * 256 + threadIdx.x;
    const int n = t >> 6, kg = t & 63;
    float a[8];
    #pragma unroll
    for (int i = 0; i < 8; i++) a[i] = W1[(size_t)(kg * 8 + i) * HID2 + n];
    uint4 H, M;
    split8_hm(a, H, M);
    __nv_bfloat16* dst = g_B + (size_t)n * 1024 + kg * 8;
    *(uint4*)(dst)       = H;
    *(uint4*)(dst + 512) = M;
}

// ============================================================================
// GEMM (proven config): z = Ah@Bh + Ah@Bm + Am@Bh.
// 2 CTAs/SM: 128 threads (4 warps), tile 128x128, stage K=32, LDA2=40.
// ============================================================================
#define LDA2  40
#define SEC_H (128 * LDA2)
#define ST_H  (4 * SEC_H)

__global__ __launch_bounds__(128, 2) void gemm_wmma_kernel() {
    extern __shared__ __align__(16) __nv_bfloat16 sm[];

    const int tid = threadIdx.x;
    const int bn = blockIdx.x;
    const int bm = blockIdx.y;
    const int wid = tid >> 5;
    const int wm = wid >> 1;
    const int wn = wid & 1;

    const int r0 = tid >> 2;
    const int c16 = tid & 3;
    const __nv_bfloat16* Abase = g_A + (size_t)(bm * 128 + r0) * 1024 + c16 * 8;
    const __nv_bfloat16* Bbase = g_B + (size_t)(bn * 128 + r0) * 1024 + c16 * 8;

    auto issue = [&](int kk, int buf) {
        const int koff = kk << 5;
        __nv_bfloat16* S = sm + buf * ST_H;
        #pragma unroll
        for (int i = 0; i < 4; i++) {
            const int rr = r0 + 32 * i;
            cp16(S +             rr * LDA2 + c16 * 8,
                 Abase + (size_t)(32 * i) * 1024 + koff);
            cp16(S + SEC_H +     rr * LDA2 + c16 * 8,
                 Abase + (size_t)(32 * i) * 1024 + 512 + koff);
            cp16(S + 2 * SEC_H + rr * LDA2 + c16 * 8,
                 Bbase + (size_t)(32 * i) * 1024 + koff);
            cp16(S + 3 * SEC_H + rr * LDA2 + c16 * 8,
                 Bbase + (size_t)(32 * i) * 1024 + 512 + koff);
        }
        CP_COMMIT();
    };

    wmma::fragment<wmma::accumulator, 16, 16, 16, float> acc[4][4];
    #pragma unroll
    for (int i = 0; i < 4; i++)
        #pragma unroll
        for (int j = 0; j < 4; j++) wmma::fill_fragment(acc[i][j], 0.0f);

    issue(0, 0);

    for (int kk = 0; kk < 16; kk++) {
        const int buf = kk & 1;
        if (kk + 1 < 16) { issue(kk + 1, buf ^ 1); CP_WAIT(1); }
        else            { CP_WAIT(0); }
        __syncthreads();

        const __nv_bfloat16* Ah = sm + buf * ST_H;
        const __nv_bfloat16* Am = Ah + SEC_H;
        const __nv_bfloat16* Bh = Ah + 2 * SEC_H;
        const __nv_bfloat16* Bm = Ah + 3 * SEC_H;

        #pragma unroll
        for (int ks = 0; ks < 2; ks++) {
            wmma::fragment<wmma::matrix_b, 16, 16, 16, __nv_bfloat16, wmma::col_major> bh[4], bmf[4];
            #pragma unroll
            for (int j = 0; j < 4; j++) {
                wmma::load_matrix_sync(bh[j],  Bh + (wn * 64 + j * 16) * LDA2 + ks * 16, LDA2);
                wmma::load_matrix_sync(bmf[j], Bm + (wn * 64 + j * 16) * LDA2 + ks * 16, LDA2);
            }
            #pragma unroll
            for (int mi = 0; mi < 4; mi++) {
                wmma::fragment<wmma::matrix_a, 16, 16, 16, __nv_bfloat16, wmma::row_major> af;
                wmma::load_matrix_sync(af, Ah + (wm * 64 + mi * 16) * LDA2 + ks * 16, LDA2);
                #pragma unroll
                for (int j = 0; j < 4; j++) wmma::mma_sync(acc[mi][j], af, bh[j], acc[mi][j]);
                #pragma unroll
                for (int j = 0; j < 4; j++) wmma::mma_sync(acc[mi][j], af, bmf[j], acc[mi][j]);
                wmma::load_matrix_sync(af, Am + (wm * 64 + mi * 16) * LDA2 + ks * 16, LDA2);
                #pragma unroll
                for (int j = 0; j < 4; j++) wmma::mma_sync(acc[mi][j], af, bh[j], acc[mi][j]);
            }
        }
        __syncthreads();
    }

    #pragma unroll
    for (int mi = 0; mi < 4; mi++) {
        const size_t row = (size_t)bm * 128 + wm * 64 + mi * 16;
        #pragma unroll
        for (int j = 0; j < 4; j++) {
            const int col = bn * 128 + wn * 64 + j * 16;
            wmma::store_matrix_sync(g_z + row * HID2 + col, acc[mi][j], HID2,
                                    wmma::mem_row_major);
        }
    }
}

// ============================================================================
// LayerNorm -> ReLU -> dot(W2) -> sigmoid (proven: warp-per-row, shuffle-only).
// ============================================================================
__device__ __forceinline__ float warp_sum(float v) {
    #pragma unroll
    for (int o = 16; o > 0; o >>= 1) v += __shfl_xor_sync(0xffffffffu, v, o);
    return v;
}

__global__ __launch_bounds__(256) void ln_head_kernel(
    const float* __restrict__ b1,
    const float* __restrict__ gamma, const float* __restrict__ beta,
    const float* __restrict__ W2, const float* __restrict__ b2)
{
    const int lane = threadIdx.x & 31;
    const size_t row = (size_t)blockIdx.x * 8 + (threadIdx.x >> 5);
    const float4* zr = (const float4*)(g_z + row * HID2);
    const float4* bp = (const float4*)b1;

    float4 v[8];
    float s = 0.0f;
    #pragma unroll
    for (int j = 0; j < 8; j++) {
        float4 t = __ldcs(zr + j * 32 + lane);
        const float4 bb = bp[j * 32 + lane];
        t.x += bb.x; t.y += bb.y; t.z += bb.z; t.w += bb.w;
        v[j] = t;
        s += t.x + t.y + t.z + t.w;
    }
    const float mu = warp_sum(s) * (1.0f / 1024.0f);

    float sq = 0.0f;
    #pragma unroll
    for (int j = 0; j < 8; j++) {
        const float d0 = v[j].x - mu, d1 = v[j].y - mu, d2 = v[j].z - mu, d3 = v[j].w - mu;
        sq += d0 * d0 + d1 * d1 + d2 * d2 + d3 * d3;
    }
    const float rstd = rsqrtf(warp_sum(sq) * (1.0f / 1024.0f) + 1e-5f);

    float a = 0.0f;
    #pragma unroll
    for (int j = 0; j < 8; j++) {
        const float4 gv = ((const float4*)gamma)[j * 32 + lane];
        const float4 bv = ((const float4*)beta)[j * 32 + lane];
        const float4 wv = ((const float4*)W2)[j * 32 + lane];
        float zn;
        zn = (v[j].x - mu) * rstd * gv.x + bv.x; if (zn > 0.0f) a += zn * wv.x;
        zn = (v[j].y - mu) * rstd * gv.y + bv.y; if (zn > 0.0f) a += zn * wv.y;
        zn = (v[j].z - mu) * rstd * gv.z + bv.z; if (zn > 0.0f) a += zn * wv.z;
        zn = (v[j].w - mu) * rstd * gv.w + bv.w; if (zn > 0.0f) a += zn * wv.w;
    }
    const float pre = warp_sum(a) + b2[0];
    if (lane == 0) g_logits[row] = 1.0f / (1.0f + expf(-pre));
}

// ============================================================================
// seg starts via boundary scan over the sorted batch ids.
// ============================================================================
__global__ void seg_starts_kernel(const int* __restrict__ batch) {
    const int i = blockIdx.x * blockDim.x + threadIdx.x;
    if (i >= NN) return;
    if (i == 0) {
        const int b0 = batch[0];
        for (int g = 0; g <= b0; g++) g_start[g] = 0;
        const int bl = batch[NN - 1];
        for (int g = bl + 1; g <= NG; g++) g_start[g] = NN;
    } else {
        const int prev = batch[i - 1], cur = batch[i];
        for (int g = prev + 1; g <= cur; g++) g_start[g] = i;
    }
}

__global__ __launch_bounds__(512) void topk_kernel() {
    __shared__ __align__(16) float sl[1028];
    const int g = blockIdx.x;
    const int s = g_start[g];
    int n = g_start[g + 1] - s;
    if (n > 1024) n = 1024;
    const int n4 = (n + 3) & ~3;
    const int k = (9 * n + 9) / 10;
    for (int i = threadIdx.x; i < n4; i += 512)
        sl[i] = (i < n) ? g_logits[s + i] : -1.0f;
    __syncthreads();
    for (int i = threadIdx.x; i < n; i += 512) {
        const float li = sl[i];
        int cnt = 0;
        for (int q = 0; q < n4; q += 4) {
            const float4 lj = *(const float4*)&sl[q];
            cnt += (lj.x > li) || (lj.x == li && (q + 0) < i);
            cnt += (lj.y > li) || (lj.y == li && (q + 1) < i);
            cnt += (lj.z > li) || (lj.z == li && (q + 2) < i);
            cnt += (lj.w > li) || (lj.w == li && (q + 3) < i);
        }
        g_keep[s + i] = (cnt < k) ? 1 : 0;
    }
}

// finalize: x_new section + logits section + zero edge section
__global__ void finalize_kernel(const float4* __restrict__ x4,
                                const float4* __restrict__ n4,
                                float* __restrict__ out)
{
    const int v = blockIdx.x * blockDim.x + threadIdx.x;
    const int node = v >> 6;
    const bool kp = g_keep[node] != 0;
    const float l = g_logits[node];
    const float4* src = kp ? x4 : n4;
    float4 r = __ldcs(src + v);
    if (kp) { r.x *= l; r.y *= l; r.z *= l; r.w *= l; }
    ((float4*)out)[v] = r;
    if ((v & 63) == 0) {
        out[OFF_L + node] = l;
        out[OFF_E + node] = 0.0f;
    }
}

// edge scatter, 4 indices per thread via int4 load
__global__ void edge_kernel(const int4* __restrict__ ei4, float* __restrict__ out) {
    const int e = blockIdx.x * blockDim.x + threadIdx.x;
    if (e < (2 * NE) / 4) {
        const int4 q = ei4[e];
        out[OFF_E + q.x] = 1.0f;
        out[OFF_E + q.y] = 1.0f;
        out[OFF_E + q.z] = 1.0f;
        out[OFF_E + q.w] = 1.0f;
    }
}

// ============================================================================
extern "C" void kernel_launch(void* const* d_in, const int* in_sizes, int n_in,
                              void* d_out, int out_size) {
    const float* h     = (const float*)d_in[0];
    const float* x     = (const float*)d_in[1];
    const float* noise = (const float*)d_in[2];
    const float* W1    = (const float*)d_in[3];
    const float* b1    = (const float*)d_in[4];
    const float* gamma = (const float*)d_in[5];
    const float* beta  = (const float*)d_in[6];
    const float* W2    = (const float*)d_in[7];
    const float* b2    = (const float*)d_in[8];
    const int*   batch = (const int*)d_in[9];
    const int*   edges = (const int*)d_in[10];
    float* out = (float*)d_out;
    (void)in_sizes; (void)n_in; (void)out_size;

    const int dyn = 2 * ST_H * (int)sizeof(__nv_bfloat16);
    cudaFuncSetAttribute(gemm_wmma_kernel, cudaFuncAttributeMaxDynamicSharedMemorySize, dyn);

    presplitA_kernel<<<(NN * 64) / 256, 256>>>(h);
    presplitB_kernel<<<(HID2 * 64) / 256, 256>>>(W1);
    gemm_wmma_kernel<<<dim3(8, 1024), 128, dyn>>>();
    ln_head_kernel<<<NN / 8, 256>>>(b1, gamma, beta, W2, b2);
    seg_starts_kernel<<<NN / 256, 256>>>(batch);
    topk_kernel<<<NG, 512>>>();
    finalize_kernel<<<(NN * 64) / 256, 256>>>((const float4*)x, (const float4*)noise, out);
    edge_kernel<<<(2 * NE / 4 + 255) / 256, 256>>>((const int4*)edges, out);
}

// round 17
// speedup vs baseline: 1.0133x; 1.0133x over previous
#include <cuda_runtime.h>
#include <cuda_bf16.h>
#include <mma.h>
#include <cstdint>

using namespace nvcuda;

#define NN      131072
#define NG      256
#define HID     512
#define HID2    1024
#define NE      2097152
#define OFF_L   ((size_t)NN * 256)
#define OFF_E   (OFF_L + NN)

// -------- scratch (device globals: allocation-free per harness rules) ------
__device__ float          g_z[(size_t)NN * HID2];        // 512 MB
__device__ float          g_logits[NN];
__device__ unsigned char  g_keep[NN];
__device__ int            g_start[NG + 1];
__device__ __align__(16) __nv_bfloat16 g_A[(size_t)NN * 1024];    // 256 MB [Ah|Am]
__device__ __align__(16) __nv_bfloat16 g_B[(size_t)HID2 * 1024];  //   2 MB [Bh|Bm]

// ======================= PTX helpers ========================================
__device__ __forceinline__ uint32_t smem_u32(const void* p) {
    uint32_t a;
    asm("{ .reg .u64 t; cvta.to.shared.u64 t, %1; cvt.u32.u64 %0, t; }" : "=r"(a) : "l"(p));
    return a;
}
__device__ __forceinline__ void cp16(void* sdst, const void* gsrc) {
    asm volatile("cp.async.cg.shared.global [%0], [%1], 16;"
                 :: "r"(smem_u32(sdst)), "l"(gsrc) : "memory");
}
#define CP_COMMIT()  asm volatile("cp.async.commit_group;" ::: "memory")
#define CP_WAIT(n)   asm volatile("cp.async.wait_group %0;" :: "n"(n) : "memory")

// ============================================================================
// Pre-split: fp32 -> (hi, mid) bf16 residual pair
// ============================================================================
__device__ __forceinline__ void split8_hm(const float* a, uint4& H, uint4& M) {
    unsigned short hb[8], mb[8];
    #pragma unroll
    for (int i = 0; i < 8; i++) {
        float f = a[i];
        __nv_bfloat16 bh = __float2bfloat16_rn(f);
        float r1 = f - __bfloat162float(bh);
        __nv_bfloat16 bm = __float2bfloat16_rn(r1);
        hb[i] = __bfloat16_as_ushort(bh);
        mb[i] = __bfloat16_as_ushort(bm);
    }
    H = make_uint4(hb[0] | (uint32_t)hb[1] << 16, hb[2] | (uint32_t)hb[3] << 16,
                   hb[4] | (uint32_t)hb[5] << 16, hb[6] | (uint32_t)hb[7] << 16);
    M = make_uint4(mb[0] | (uint32_t)mb[1] << 16, mb[2] | (uint32_t)mb[3] << 16,
                   mb[4] | (uint32_t)mb[5] << 16, mb[6] | (uint32_t)mb[7] << 16);
}

__global__ __launch_bounds__(256) void presplitA_kernel(const float* __restrict__ h) {
    const size_t t = (size_t)blockIdx.x * 256 + threadIdx.x;
    const int row = (int)(t >> 6), kg = (int)(t & 63);
    float a[8];
    *(float4*)&a[0] = __ldcs((const float4*)(h + (size_t)row * HID + kg * 8));
    *(float4*)&a[4] = __ldcs((const float4*)(h + (size_t)row * HID + kg * 8 + 4));
    uint4 H, M;
    split8_hm(a, H, M);
    __nv_bfloat16* dst = g_A + (size_t)row * 1024 + kg * 8;
    *(uint4*)(dst)       = H;
    *(uint4*)(dst + 512) = M;
}

__global__ __launch_bounds__(256) void presplitB_kernel(const float* __restrict__ W1) {
    const int t = blockIdx.x * 256 + threadIdx.x;
    const int n = t >> 6, kg = t & 63;
    float a[8];
    #pragma unroll
    for (int i = 0; i < 8; i++) a[i] = W1[(size_t)(kg * 8 + i) * HID2 + n];
    uint4 H, M;
    split8_hm(a, H, M);
    __nv_bfloat16* dst = g_B + (size_t)n * 1024 + kg * 8;
    *(uint4*)(dst)       = H;
    *(uint4*)(dst + 512) = M;
}

// ============================================================================
// GEMM: z = Ah@Bh + Ah@Bm + Am@Bh.  Single-barrier mainloop:
//   CP_WAIT(0) -> BAR -> issue(kk+1, buf^1) -> compute(buf)
// BAR guarantees all warps finished compute(kk-1) (the readers of buf^1)
// before refill; fill of stage kk had the full compute(kk-1) phase to land.
// 2 CTAs/SM: 128 threads (4 warps), tile 128x128, stage K=32, LDA2=40.
// ============================================================================
#define LDA2  40
#define SEC_H (128 * LDA2)
#define ST_H  (4 * SEC_H)

__global__ __launch_bounds__(128, 2) void gemm_wmma_kernel() {
    extern __shared__ __align__(16) __nv_bfloat16 sm[];

    const int tid = threadIdx.x;
    const int bn = blockIdx.x;
    const int bm = blockIdx.y;
    const int wid = tid >> 5;
    const int wm = wid >> 1;
    const int wn = wid & 1;

    const int r0 = tid >> 2;
    const int c16 = tid & 3;
    const __nv_bfloat16* Abase = g_A + (size_t)(bm * 128 + r0) * 1024 + c16 * 8;
    const __nv_bfloat16* Bbase = g_B + (size_t)(bn * 128 + r0) * 1024 + c16 * 8;

    auto issue = [&](int kk, int buf) {
        const int koff = kk << 5;
        __nv_bfloat16* S = sm + buf * ST_H;
        #pragma unroll
        for (int i = 0; i < 4; i++) {
            const int rr = r0 + 32 * i;
            cp16(S +             rr * LDA2 + c16 * 8,
                 Abase + (size_t)(32 * i) * 1024 + koff);
            cp16(S + SEC_H +     rr * LDA2 + c16 * 8,
                 Abase + (size_t)(32 * i) * 1024 + 512 + koff);
            cp16(S + 2 * SEC_H + rr * LDA2 + c16 * 8,
                 Bbase + (size_t)(32 * i) * 1024 + koff);
            cp16(S + 3 * SEC_H + rr * LDA2 + c16 * 8,
                 Bbase + (size_t)(32 * i) * 1024 + 512 + koff);
        }
        CP_COMMIT();
    };

    wmma::fragment<wmma::accumulator, 16, 16, 16, float> acc[4][4];
    #pragma unroll
    for (int i = 0; i < 4; i++)
        #pragma unroll
        for (int j = 0; j < 4; j++) wmma::fill_fragment(acc[i][j], 0.0f);

    issue(0, 0);

    for (int kk = 0; kk < 16; kk++) {
        const int buf = kk & 1;
        CP_WAIT(0);                      // stage kk landed (issued iter kk-1)
        __syncthreads();                 // + all warps done reading buf^1 (iter kk-1)
        if (kk + 1 < 16) issue(kk + 1, buf ^ 1);   // overlaps compute below

        const __nv_bfloat16* Ah = sm + buf * ST_H;
        const __nv_bfloat16* Am = Ah + SEC_H;
        const __nv_bfloat16* Bh = Ah + 2 * SEC_H;
        const __nv_bfloat16* Bm = Ah + 3 * SEC_H;

        #pragma unroll
        for (int ks = 0; ks < 2; ks++) {
            wmma::fragment<wmma::matrix_b, 16, 16, 16, __nv_bfloat16, wmma::col_major> bh[4], bmf[4];
            #pragma unroll
            for (int j = 0; j < 4; j++) {
                wmma::load_matrix_sync(bh[j],  Bh + (wn * 64 + j * 16) * LDA2 + ks * 16, LDA2);
                wmma::load_matrix_sync(bmf[j], Bm + (wn * 64 + j * 16) * LDA2 + ks * 16, LDA2);
            }
            #pragma unroll
            for (int mi = 0; mi < 4; mi++) {
                wmma::fragment<wmma::matrix_a, 16, 16, 16, __nv_bfloat16, wmma::row_major> af;
                wmma::load_matrix_sync(af, Ah + (wm * 64 + mi * 16) * LDA2 + ks * 16, LDA2);
                #pragma unroll
                for (int j = 0; j < 4; j++) wmma::mma_sync(acc[mi][j], af, bh[j], acc[mi][j]);
                #pragma unroll
                for (int j = 0; j < 4; j++) wmma::mma_sync(acc[mi][j], af, bmf[j], acc[mi][j]);
                wmma::load_matrix_sync(af, Am + (wm * 64 + mi * 16) * LDA2 + ks * 16, LDA2);
                #pragma unroll
                for (int j = 0; j < 4; j++) wmma::mma_sync(acc[mi][j], af, bh[j], acc[mi][j]);
            }
        }
    }

    #pragma unroll
    for (int mi = 0; mi < 4; mi++) {
        const size_t row = (size_t)bm * 128 + wm * 64 + mi * 16;
        #pragma unroll
        for (int j = 0; j < 4; j++) {
            const int col = bn * 128 + wn * 64 + j * 16;
            wmma::store_matrix_sync(g_z + row * HID2 + col, acc[mi][j], HID2,
                                    wmma::mem_row_major);
        }
    }
}

// ============================================================================
// LayerNorm -> ReLU -> dot(W2) -> sigmoid (proven: warp-per-row, shuffle-only).
// ============================================================================
__device__ __forceinline__ float warp_sum(float v) {
    #pragma unroll
    for (int o = 16; o > 0; o >>= 1) v += __shfl_xor_sync(0xffffffffu, v, o);
    return v;
}

__global__ __launch_bounds__(256) void ln_head_kernel(
    const float* __restrict__ b1,
    const float* __restrict__ gamma, const float* __restrict__ beta,
    const float* __restrict__ W2, const float* __restrict__ b2)
{
    const int lane = threadIdx.x & 31;
    const size_t row = (size_t)blockIdx.x * 8 + (threadIdx.x >> 5);
    const float4* zr = (const float4*)(g_z + row * HID2);
    const float4* bp = (const float4*)b1;

    float4 v[8];
    float s = 0.0f;
    #pragma unroll
    for (int j = 0; j < 8; j++) {
        float4 t = __ldcs(zr + j * 32 + lane);
        const float4 bb = bp[j * 32 + lane];
        t.x += bb.x; t.y += bb.y; t.z += bb.z; t.w += bb.w;
        v[j] = t;
        s += t.x + t.y + t.z + t.w;
    }
    const float mu = warp_sum(s) * (1.0f / 1024.0f);

    float sq = 0.0f;
    #pragma unroll
    for (int j = 0; j < 8; j++) {
        const float d0 = v[j].x - mu, d1 = v[j].y - mu, d2 = v[j].z - mu, d3 = v[j].w - mu;
        sq += d0 * d0 + d1 * d1 + d2 * d2 + d3 * d3;
    }
    const float rstd = rsqrtf(warp_sum(sq) * (1.0f / 1024.0f) + 1e-5f);

    float a = 0.0f;
    #pragma unroll
    for (int j = 0; j < 8; j++) {
        const float4 gv = ((const float4*)gamma)[j * 32 + lane];
        const float4 bv = ((const float4*)beta)[j * 32 + lane];
        const float4 wv = ((const float4*)W2)[j * 32 + lane];
        float zn;
        zn = (v[j].x - mu) * rstd * gv.x + bv.x; if (zn > 0.0f) a += zn * wv.x;
        zn = (v[j].y - mu) * rstd * gv.y + bv.y; if (zn > 0.0f) a += zn * wv.y;
        zn = (v[j].z - mu) * rstd * gv.z + bv.z; if (zn > 0.0f) a += zn * wv.z;
        zn = (v[j].w - mu) * rstd * gv.w + bv.w; if (zn > 0.0f) a += zn * wv.w;
    }
    const float pre = warp_sum(a) + b2[0];
    if (lane == 0) g_logits[row] = 1.0f / (1.0f + expf(-pre));
}

// ============================================================================
// seg starts via boundary scan over the sorted batch ids.
// ============================================================================
__global__ void seg_starts_kernel(const int* __restrict__ batch) {
    const int i = blockIdx.x * blockDim.x + threadIdx.x;
    if (i >= NN) return;
    if (i == 0) {
        const int b0 = batch[0];
        for (int g = 0; g <= b0; g++) g_start[g] = 0;
        const int bl = batch[NN - 1];
        for (int g = bl + 1; g <= NG; g++) g_start[g] = NN;
    } else {
        const int prev = batch[i - 1], cur = batch[i];
        for (int g = prev + 1; g <= cur; g++) g_start[g] = i;
    }
}

__global__ __launch_bounds__(512) void topk_kernel() {
    __shared__ __align__(16) float sl[1028];
    const int g = blockIdx.x;
    const int s = g_start[g];
    int n = g_start[g + 1] - s;
    if (n > 1024) n = 1024;
    const int n4 = (n + 3) & ~3;
    const int k = (9 * n + 9) / 10;
    for (int i = threadIdx.x; i < n4; i += 512)
        sl[i] = (i < n) ? g_logits[s + i] : -1.0f;
    __syncthreads();
    for (int i = threadIdx.x; i < n; i += 512) {
        const float li = sl[i];
        int cnt = 0;
        for (int q = 0; q < n4; q += 4) {
            const float4 lj = *(const float4*)&sl[q];
            cnt += (lj.x > li) || (lj.x == li && (q + 0) < i);
            cnt += (lj.y > li) || (lj.y == li && (q + 1) < i);
            cnt += (lj.z > li) || (lj.z == li && (q + 2) < i);
            cnt += (lj.w > li) || (lj.w == li && (q + 3) < i);
        }
        g_keep[s + i] = (cnt < k) ? 1 : 0;
    }
}

// finalize: x_new section + logits section + zero edge section
__global__ void finalize_kernel(const float4* __restrict__ x4,
                                const float4* __restrict__ n4,
                                float* __restrict__ out)
{
    const int v = blockIdx.x * blockDim.x + threadIdx.x;
    const int node = v >> 6;
    const bool kp = g_keep[node] != 0;
    const float l = g_logits[node];
    const float4* src = kp ? x4 : n4;
    float4 r = __ldcs(src + v);
    if (kp) { r.x *= l; r.y *= l; r.z *= l; r.w *= l; }
    ((float4*)out)[v] = r;
    if ((v & 63) == 0) {
        out[OFF_L + node] = l;
        out[OFF_E + node] = 0.0f;
    }
}

// edge scatter, 4 indices per thread via int4 load
__global__ void edge_kernel(const int4* __restrict__ ei4, float* __restrict__ out) {
    const int e = blockIdx.x * blockDim.x + threadIdx.x;
    if (e < (2 * NE) / 4) {
        const int4 q = ei4[e];
        out[OFF_E + q.x] = 1.0f;
        out[OFF_E + q.y] = 1.0f;
        out[OFF_E + q.z] = 1.0f;
        out[OFF_E + q.w] = 1.0f;
    }
}

// ============================================================================
extern "C" void kernel_launch(void* const* d_in, const int* in_sizes, int n_in,
                              void* d_out, int out_size) {
    const float* h     = (const float*)d_in[0];
    const float* x     = (const float*)d_in[1];
    const float* noise = (const float*)d_in[2];
    const float* W1    = (const float*)d_in[3];
    const float* b1    = (const float*)d_in[4];
    const float* gamma = (const float*)d_in[5];
    const float* beta  = (const float*)d_in[6];
    const float* W2    = (const float*)d_in[7];
    const float* b2    = (const float*)d_in[8];
    const int*   batch = (const int*)d_in[9];
    const int*   edges = (const int*)d_in[10];
    float* out = (float*)d_out;
    (void)in_sizes; (void)n_in; (void)out_size;

    const int dyn = 2 * ST_H * (int)sizeof(__nv_bfloat16);
    cudaFuncSetAttribute(gemm_wmma_kernel, cudaFuncAttributeMaxDynamicSharedMemorySize, dyn);

    presplitA_kernel<<<(NN * 64) / 256, 256>>>(h);
    presplitB_kernel<<<(HID2 * 64) / 256, 256>>>(W1);
    gemm_wmma_kernel<<<dim3(8, 1024), 128, dyn>>>();
    ln_head_kernel<<<NN / 8, 256>>>(b1, gamma, beta, W2, b2);
    seg_starts_kernel<<<NN / 256, 256>>>(batch);
    topk_kernel<<<NG, 512>>>();
    finalize_kernel<<<(NN * 64) / 256, 256>>>((const float4*)x, (const float4*)noise, out);
    edge_kernel<<<(2 * NE / 4 + 255) / 256, 256>>>((const int4*)edges, out);
}